// round 6
// baseline (speedup 1.0000x reference)
#include <cuda_runtime.h>
#include <cuda_bf16.h>
#include <cstdint>

#define H_HEADS 16
#define DHEAD   64
#define RMS_EPS 1.1920928955078125e-07f
#define MAXTOK  4096
#define LOG2E   1.4426950408889634f

// ---------------- scratch ----------------
__device__ __nv_bfloat16 g_ahi [MAXTOK * 1024];
__device__ __nv_bfloat16 g_alo [MAXTOK * 1024];
__device__ __nv_bfloat16 g_bhi [1024 * 1024];
__device__ __nv_bfloat16 g_blo [1024 * 1024];
__device__ __nv_bfloat16 g_qhi [MAXTOK * 1024];
__device__ __nv_bfloat16 g_qlo [MAXTOK * 1024];
__device__ __nv_bfloat16 g_kvhi[MAXTOK * 1024];
__device__ __nv_bfloat16 g_kvlo[MAXTOK * 1024];

// ---------------- helpers ----------------
__device__ __forceinline__ uint32_t smem_u32(const void* p) {
    uint32_t a;
    asm("{ .reg .u64 t; cvta.to.shared.u64 t, %1; cvt.u32.u64 %0, t; }" : "=r"(a) : "l"(p));
    return a;
}

#define LDSM_X4(r0, r1, r2, r3, addr) \
    asm volatile("ldmatrix.sync.aligned.m8n8.x4.shared.b16 {%0,%1,%2,%3}, [%4];" \
                 : "=r"(r0), "=r"(r1), "=r"(r2), "=r"(r3) : "r"(addr))

#define LDSM_X4_T(r0, r1, r2, r3, addr) \
    asm volatile("ldmatrix.sync.aligned.m8n8.x4.trans.shared.b16 {%0,%1,%2,%3}, [%4];" \
                 : "=r"(r0), "=r"(r1), "=r"(r2), "=r"(r3) : "r"(addr))

#define MMA_BF16(c0, c1, c2, c3, a0, a1, a2, a3, b0, b1) \
    asm volatile("mma.sync.aligned.m16n8k16.row.col.f32.bf16.bf16.f32 " \
                 "{%0,%1,%2,%3}, {%4,%5,%6,%7}, {%8,%9}, {%0,%1,%2,%3};" \
                 : "+f"(c0), "+f"(c1), "+f"(c2), "+f"(c3) \
                 : "r"(a0), "r"(a1), "r"(a2), "r"(a3), "r"(b0), "r"(b1))

#define CP16(saddr, gptr) \
    asm volatile("cp.async.cg.shared.global [%0], [%1], 16;" :: "r"(saddr), "l"(gptr))
#define CP_COMMIT() asm volatile("cp.async.commit_group;" ::: "memory")
#define CP_WAIT1()  asm volatile("cp.async.wait_group 1;" ::: "memory")
#define CP_WAIT0()  asm volatile("cp.async.wait_group 0;" ::: "memory")

__device__ __forceinline__ uint32_t pack_bf2(__nv_bfloat16 a, __nv_bfloat16 b) {
    __nv_bfloat162 t(a, b);
    return *(uint32_t*)&t;
}
__device__ __forceinline__ void split_pack(float x, float y, uint32_t& hi, uint32_t& lo) {
    __nv_bfloat16 hx = __float2bfloat16(x), hy = __float2bfloat16(y);
    __nv_bfloat16 lx = __float2bfloat16(x - __bfloat162float(hx));
    __nv_bfloat16 ly = __float2bfloat16(y - __bfloat162float(hy));
    hi = pack_bf2(hx, hy);
    lo = pack_bf2(lx, ly);
}

// ---------------------------------------------------------------------------
// split fp32 -> bf16 hi + bf16 lo (weights)
// ---------------------------------------------------------------------------
__global__ __launch_bounds__(256) void split_bf16(
    const float* __restrict__ in, __nv_bfloat16* __restrict__ hi,
    __nv_bfloat16* __restrict__ lo, int n4)
{
    int i = blockIdx.x * blockDim.x + threadIdx.x;
    if (i >= n4) return;
    float4 v = ((const float4*)in)[i];
    uint32_t h0, l0, h1, l1;
    split_pack(v.x, v.y, h0, l0);
    split_pack(v.z, v.w, h1, l1);
    ((uint32_t*)hi)[2 * i]     = h0;
    ((uint32_t*)hi)[2 * i + 1] = h1;
    ((uint32_t*)lo)[2 * i]     = l0;
    ((uint32_t*)lo)[2 * i + 1] = l1;
}

// ---------------------------------------------------------------------------
// prep_q: x -> raw split [M,C] + roped/rms/scaled q split [B,H,T,D]
// ---------------------------------------------------------------------------
__global__ __launch_bounds__(256) void prep_q(
    const float* __restrict__ x, const float* __restrict__ cosb,
    const float* __restrict__ sinb,
    __nv_bfloat16* __restrict__ ahi, __nv_bfloat16* __restrict__ alo,
    __nv_bfloat16* __restrict__ qhi, __nv_bfloat16* __restrict__ qlo,
    float qscale, int T, int total_heads)
{
    int w = blockIdx.x * 8 + (threadIdx.x >> 5);
    if (w >= total_heads) return;
    int lane = threadIdx.x & 31;
    int h = w % H_HEADS;
    int t = (w / H_HEADS) % T;
    int b = w / (H_HEADS * T);

    size_t ibase = (size_t)w * DHEAD;
    float x1 = x[ibase + lane];
    float x2 = x[ibase + 32 + lane];

    {
        __nv_bfloat16 h1 = __float2bfloat16(x1);
        __nv_bfloat16 h2 = __float2bfloat16(x2);
        ahi[ibase + lane]      = h1;
        ahi[ibase + 32 + lane] = h2;
        alo[ibase + lane]      = __float2bfloat16(x1 - __bfloat162float(h1));
        alo[ibase + 32 + lane] = __float2bfloat16(x2 - __bfloat162float(h2));
    }

    float c  = cosb[t * 32 + lane];
    float s  = sinb[t * 32 + lane];
    float o1 = x1 * c + x2 * s;
    float o2 = -x1 * s + x2 * c;

    float ss = o1 * o1 + o2 * o2;
#pragma unroll
    for (int off = 16; off; off >>= 1)
        ss += __shfl_xor_sync(0xffffffffu, ss, off);
    float r = rsqrtf(ss * (1.0f / 64.0f) + RMS_EPS) * qscale;

    o1 *= r; o2 *= r;
    __nv_bfloat16 h1 = __float2bfloat16(o1);
    __nv_bfloat16 h2 = __float2bfloat16(o2);
    size_t obase = ((size_t)(b * H_HEADS + h) * T + t) * DHEAD;
    qhi[obase + lane]      = h1;
    qhi[obase + 32 + lane] = h2;
    qlo[obase + lane]      = __float2bfloat16(o1 - __bfloat162float(h1));
    qlo[obase + 32 + lane] = __float2bfloat16(o2 - __bfloat162float(h2));
}

// ---------------------------------------------------------------------------
// cp.async double-buffered split-precision NT GEMM (from R5)
// ---------------------------------------------------------------------------
#define KCH2   32
#define ROWB2  80
#define MATB2  (128 * ROWB2)
#define STB2   (4 * MATB2)
#define GEMM_SMEM (2 * STB2)

template <bool FUSE_ROPE>
__global__ __launch_bounds__(256) void gemm_mma(
    const __nv_bfloat16* __restrict__ Ahi, const __nv_bfloat16* __restrict__ Alo,
    const __nv_bfloat16* __restrict__ Bhi, const __nv_bfloat16* __restrict__ Blo,
    float* __restrict__ C,
    const float* __restrict__ cosb, const float* __restrict__ sinb,
    __nv_bfloat16* __restrict__ Ohi, __nv_bfloat16* __restrict__ Olo,
    int M, int N, int K, int T)
{
    extern __shared__ char smem[];
    const uint32_t sb = smem_u32(smem);

    const int tid  = threadIdx.x;
    const int wid  = tid >> 5;
    const int lane = tid & 31;
    const int m0 = blockIdx.y * 128, n0 = blockIdx.x * 128;

    const int wm = (wid & 3) * 32;
    const int wn = (wid >> 2) * 64;

    const int a_row = (lane & 7) + (lane & 8);
    const int a_col = (lane >> 4) * 16;
    const int b_row = (lane & 7) + ((lane >> 4) & 1) * 8;
    const int b_col = ((lane >> 3) & 1) * 16;

    const int grow = tid >> 1;
    const uint32_t s_off = (uint32_t)grow * ROWB2 + (tid & 1) * 32;
    const int gelem = (tid & 1) * 16;

    const __nv_bfloat16* gAh = Ahi + (size_t)(m0 + grow) * K + gelem;
    const __nv_bfloat16* gAl = Alo + (size_t)(m0 + grow) * K + gelem;
    const __nv_bfloat16* gBh = Bhi + (size_t)(n0 + grow) * K + gelem;
    const __nv_bfloat16* gBl = Blo + (size_t)(n0 + grow) * K + gelem;

    float c[2][8][4];
#pragma unroll
    for (int i = 0; i < 2; i++)
#pragma unroll
        for (int j = 0; j < 8; j++)
#pragma unroll
            for (int e = 0; e < 4; e++) c[i][j][e] = 0.f;

    const int nchunk = K / KCH2;

    auto fill = [&](int stage, int ch) {
        const int k0 = ch * KCH2;
        uint32_t s0 = sb + stage * STB2 + s_off;
        const __nv_bfloat16* a0 = gAh + k0;
        const __nv_bfloat16* a1 = gAl + k0;
        const __nv_bfloat16* b0 = gBh + k0;
        const __nv_bfloat16* b1 = gBl + k0;
        CP16(s0,                 a0);      CP16(s0 + 16,                 a0 + 8);
        CP16(s0 + MATB2,         a1);      CP16(s0 + MATB2 + 16,         a1 + 8);
        CP16(s0 + 2 * MATB2,     b0);      CP16(s0 + 2 * MATB2 + 16,     b0 + 8);
        CP16(s0 + 3 * MATB2,     b1);      CP16(s0 + 3 * MATB2 + 16,     b1 + 8);
    };

    fill(0, 0);
    CP_COMMIT();

    for (int ch = 0; ch < nchunk; ch++) {
        const int st = ch & 1;
        if (ch + 1 < nchunk) { fill(st ^ 1, ch + 1); CP_COMMIT(); CP_WAIT1(); }
        else                 { CP_WAIT0(); }
        __syncthreads();

        const uint32_t base = sb + st * STB2;
        const uint32_t sAhi = base, sBhi = base + 2 * MATB2;

#pragma unroll
        for (int ks = 0; ks < 2; ks++) {
            const int kb = ks * 32;
            uint32_t ah[2][4], al[2][4], bh[4][4], bl[4][4];
#pragma unroll
            for (int mi = 0; mi < 2; mi++) {
                uint32_t addr = sAhi + (uint32_t)(wm + mi * 16 + a_row) * ROWB2 + kb + a_col;
                LDSM_X4(ah[mi][0], ah[mi][1], ah[mi][2], ah[mi][3], addr);
                addr += MATB2;
                LDSM_X4(al[mi][0], al[mi][1], al[mi][2], al[mi][3], addr);
            }
#pragma unroll
            for (int nb = 0; nb < 4; nb++) {
                uint32_t addr = sBhi + (uint32_t)(wn + nb * 16 + b_row) * ROWB2 + kb + b_col;
                LDSM_X4(bh[nb][0], bh[nb][1], bh[nb][2], bh[nb][3], addr);
                addr += MATB2;
                LDSM_X4(bl[nb][0], bl[nb][1], bl[nb][2], bl[nb][3], addr);
            }
#pragma unroll
            for (int mi = 0; mi < 2; mi++)
#pragma unroll
                for (int nb = 0; nb < 4; nb++)
#pragma unroll
                    for (int sj = 0; sj < 2; sj++) {
                        float* cc = c[mi][nb * 2 + sj];
                        MMA_BF16(cc[0], cc[1], cc[2], cc[3],
                                 ah[mi][0], ah[mi][1], ah[mi][2], ah[mi][3],
                                 bh[nb][sj * 2], bh[nb][sj * 2 + 1]);
                        MMA_BF16(cc[0], cc[1], cc[2], cc[3],
                                 ah[mi][0], ah[mi][1], ah[mi][2], ah[mi][3],
                                 bl[nb][sj * 2], bl[nb][sj * 2 + 1]);
                        MMA_BF16(cc[0], cc[1], cc[2], cc[3],
                                 al[mi][0], al[mi][1], al[mi][2], al[mi][3],
                                 bh[nb][sj * 2], bh[nb][sj * 2 + 1]);
                    }
        }
        __syncthreads();
    }

    const int g  = lane >> 2;
    const int t2 = (lane & 3) * 2;

    if (!FUSE_ROPE) {
#pragma unroll
        for (int mi = 0; mi < 2; mi++) {
            float* r0 = C + (size_t)(m0 + wm + mi * 16 + g) * N + n0 + wn + t2;
            float* r1 = r0 + 8 * N;
#pragma unroll
            for (int nj = 0; nj < 8; nj++) {
                *(float2*)(r0 + nj * 8) = make_float2(c[mi][nj][0], c[mi][nj][1]);
                *(float2*)(r1 + nj * 8) = make_float2(c[mi][nj][2], c[mi][nj][3]);
            }
        }
    } else {
        const int h = (n0 + wn) >> 6;
#pragma unroll
        for (int mi = 0; mi < 2; mi++) {
#pragma unroll
            for (int half = 0; half < 2; half++) {
                const int m = m0 + wm + mi * 16 + g + half * 8;
                const int b = m / T, t = m % T;
                float o1[4][2], o2[4][2];
                float ss = 0.f;
#pragma unroll
                for (int nj = 0; nj < 4; nj++) {
#pragma unroll
                    for (int e = 0; e < 2; e++) {
                        const int d = nj * 8 + t2 + e;
                        float x1 = c[mi][nj][half * 2 + e];
                        float x2 = c[mi][nj + 4][half * 2 + e];
                        float co = cosb[t * 32 + d];
                        float si = sinb[t * 32 + d];
                        float a = x1 * co + x2 * si;
                        float bb = -x1 * si + x2 * co;
                        o1[nj][e] = a; o2[nj][e] = bb;
                        ss += a * a + bb * bb;
                    }
                }
                ss += __shfl_xor_sync(0xffffffffu, ss, 1);
                ss += __shfl_xor_sync(0xffffffffu, ss, 2);
                float r = rsqrtf(ss * (1.0f / 64.0f) + RMS_EPS);
                const size_t ob = ((size_t)(b * H_HEADS + h) * T + t) * DHEAD + t2;
#pragma unroll
                for (int nj = 0; nj < 4; nj++) {
                    uint32_t hi, lo;
                    split_pack(o1[nj][0] * r, o1[nj][1] * r, hi, lo);
                    *(uint32_t*)(Ohi + ob + nj * 8) = hi;
                    *(uint32_t*)(Olo + ob + nj * 8) = lo;
                    split_pack(o2[nj][0] * r, o2[nj][1] * r, hi, lo);
                    *(uint32_t*)(Ohi + ob + 32 + nj * 8) = hi;
                    *(uint32_t*)(Olo + ob + 32 + nj * 8) = lo;
                }
            }
        }
    }
}

// ---------------------------------------------------------------------------
// Tensor-core sliding-window flash attention, cp.async double-buffered KV.
// ---------------------------------------------------------------------------
#define ATT_ROWB 144
#define ATT_MAT  (64 * ATT_ROWB)     // 9216 B (one matrix: 64 rows x 128B + pad)
#define ATT_STB  (2 * ATT_MAT)       // hi + lo per stage

__global__ __launch_bounds__(128) void attn_mma(
    const __nv_bfloat16* __restrict__ Qhi, const __nv_bfloat16* __restrict__ Qlo,
    const __nv_bfloat16* __restrict__ KVhi, const __nv_bfloat16* __restrict__ KVlo,
    __nv_bfloat16* __restrict__ Ohi, __nv_bfloat16* __restrict__ Olo,
    const int* __restrict__ wl, int T)
{
    __shared__ char smc[2 * ATT_STB];
    const uint32_t sb = smem_u32(smc);

    const int tid = threadIdx.x, wid = tid >> 5, lane = tid & 31;
    const int qt = blockIdx.x, h = blockIdx.y, b = blockIdx.z;
    const int q0 = qt * 64;
    const int W = *wl;
    const size_t hb = (size_t)(b * H_HEADS + h) * T * DHEAD;

    // fill mapping: row = tid>>1 (0..63), half = tid&1 (64B each)
    const int frow = tid >> 1;
    const uint32_t f_soff = (uint32_t)frow * ATT_ROWB + (tid & 1) * 64;
    const int f_gel = (tid & 1) * 32;

    const int a_row  = (lane & 7) + (lane & 8);
    const int a_colB = (lane >> 4) * 16;
    const int b_row  = (lane & 7) + ((lane >> 4) & 1) * 8;
    const int b_colB = ((lane >> 3) & 1) * 16;
    const int t_m = lane >> 3, t_r = lane & 7;

    auto fill_kv = [&](int st, int k0) {
        uint32_t s0 = sb + st * ATT_STB + f_soff;
        const __nv_bfloat16* gh = KVhi + hb + (size_t)(k0 + frow) * DHEAD + f_gel;
        const __nv_bfloat16* gl = KVlo + hb + (size_t)(k0 + frow) * DHEAD + f_gel;
        CP16(s0,      gh);      CP16(s0 + 16,      gh + 8);
        CP16(s0 + 32, gh + 16); CP16(s0 + 48,      gh + 24);
        s0 += ATT_MAT;
        CP16(s0,      gl);      CP16(s0 + 16,      gl + 8);
        CP16(s0 + 32, gl + 16); CP16(s0 + 48,      gl + 24);
    };

    // ---- stage Q through stage-0 buffer -> fragments ----
    {
        uint32_t s0 = sb + f_soff;
        const __nv_bfloat16* gh = Qhi + hb + (size_t)(q0 + frow) * DHEAD + f_gel;
        const __nv_bfloat16* gl = Qlo + hb + (size_t)(q0 + frow) * DHEAD + f_gel;
        CP16(s0,      gh);      CP16(s0 + 16,      gh + 8);
        CP16(s0 + 32, gh + 16); CP16(s0 + 48,      gh + 24);
        uint32_t s1 = s0 + ATT_MAT;
        CP16(s1,      gl);      CP16(s1 + 16,      gl + 8);
        CP16(s1 + 32, gl + 16); CP16(s1 + 48,      gl + 24);
        CP_COMMIT();
        CP_WAIT0();
    }
    __syncthreads();
    uint32_t qh[4][4], ql[4][4];
#pragma unroll
    for (int kc = 0; kc < 4; kc++) {
        uint32_t ad = sb + (uint32_t)(wid * 16 + a_row) * ATT_ROWB + kc * 32 + a_colB;
        LDSM_X4(qh[kc][0], qh[kc][1], qh[kc][2], qh[kc][3], ad);
        LDSM_X4(ql[kc][0], ql[kc][1], ql[kc][2], ql[kc][3], ad + ATT_MAT);
    }
    __syncthreads();

    float o[8][4];
#pragma unroll
    for (int i = 0; i < 8; i++)
#pragma unroll
        for (int e = 0; e < 4; e++) o[i][e] = 0.f;
    float mrow[2] = {-1e30f, -1e30f};
    float lrw[2]  = {0.f, 0.f};

    int lo_t = q0 - W; if (lo_t < 0) lo_t = 0;
    const int kt_lo = lo_t >> 6;

    fill_kv(0, kt_lo * 64);
    CP_COMMIT();

    for (int kt = kt_lo; kt <= qt; kt++) {
        const int k0 = kt * 64;
        const int st = (kt - kt_lo) & 1;
        if (kt < qt) { fill_kv(st ^ 1, k0 + 64); CP_COMMIT(); CP_WAIT1(); }
        else         { CP_WAIT0(); }
        __syncthreads();

        const uint32_t sKhi = sb + st * ATT_STB;

        float s[8][4];
#pragma unroll
        for (int i = 0; i < 8; i++)
#pragma unroll
            for (int e = 0; e < 4; e++) s[i][e] = 0.f;

#pragma unroll
        for (int n16 = 0; n16 < 4; n16++) {
            uint32_t bh[4][4], bl[4][4];
#pragma unroll
            for (int kc = 0; kc < 4; kc++) {
                uint32_t ad = sKhi + (uint32_t)(n16 * 16 + b_row) * ATT_ROWB + kc * 32 + b_colB;
                LDSM_X4(bh[kc][0], bh[kc][1], bh[kc][2], bh[kc][3], ad);
                LDSM_X4(bl[kc][0], bl[kc][1], bl[kc][2], bl[kc][3], ad + ATT_MAT);
            }
#pragma unroll
            for (int kc = 0; kc < 4; kc++)
#pragma unroll
                for (int sj = 0; sj < 2; sj++) {
                    float* cc = s[n16 * 2 + sj];
                    MMA_BF16(cc[0], cc[1], cc[2], cc[3],
                             qh[kc][0], qh[kc][1], qh[kc][2], qh[kc][3],
                             bh[kc][sj * 2], bh[kc][sj * 2 + 1]);
                    MMA_BF16(cc[0], cc[1], cc[2], cc[3],
                             qh[kc][0], qh[kc][1], qh[kc][2], qh[kc][3],
                             bl[kc][sj * 2], bl[kc][sj * 2 + 1]);
                    MMA_BF16(cc[0], cc[1], cc[2], cc[3],
                             ql[kc][0], ql[kc][1], ql[kc][2], ql[kc][3],
                             bh[kc][sj * 2], bh[kc][sj * 2 + 1]);
                }
        }

        const bool fullt = (kt < qt) && (q0 + 63 - k0 <= W);
        if (!fullt) {
            const int qr = q0 + wid * 16 + (lane >> 2);
#pragma unroll
            for (int nb = 0; nb < 8; nb++) {
                const int kb = k0 + nb * 8 + (lane & 3) * 2;
#pragma unroll
                for (int e = 0; e < 4; e++) {
                    int qq = qr + ((e >= 2) ? 8 : 0);
                    int kk = kb + (e & 1);
                    if (kk > qq || qq - kk > W) s[nb][e] = -1e30f;
                }
            }
        }

        uint32_t ph[4][4], pl[4][4];
#pragma unroll
        for (int r = 0; r < 2; r++) {
            float mx = -1e30f;
#pragma unroll
            for (int nb = 0; nb < 8; nb++)
                mx = fmaxf(mx, fmaxf(s[nb][r * 2], s[nb][r * 2 + 1]));
            mx = fmaxf(mx, __shfl_xor_sync(0xffffffffu, mx, 1));
            mx = fmaxf(mx, __shfl_xor_sync(0xffffffffu, mx, 2));
            float mn = fmaxf(mrow[r], mx);
            float alpha = exp2f(mrow[r] - mn);
            mrow[r] = mn;
            float rs = 0.f;
#pragma unroll
            for (int nb = 0; nb < 8; nb++) {
#pragma unroll
                for (int e = 0; e < 2; e++) {
                    float v = s[nb][r * 2 + e];
                    float p = (v <= -1e29f) ? 0.f : exp2f(v - mn);
                    s[nb][r * 2 + e] = p;
                    rs += p;
                }
            }
            rs += __shfl_xor_sync(0xffffffffu, rs, 1);
            rs += __shfl_xor_sync(0xffffffffu, rs, 2);
            lrw[r] = lrw[r] * alpha + rs;
#pragma unroll
            for (int nj = 0; nj < 8; nj++) {
                o[nj][r * 2]     *= alpha;
                o[nj][r * 2 + 1] *= alpha;
            }
        }

#pragma unroll
        for (int kk = 0; kk < 4; kk++) {
            split_pack(s[2 * kk][0],     s[2 * kk][1],     ph[kk][0], pl[kk][0]);
            split_pack(s[2 * kk][2],     s[2 * kk][3],     ph[kk][1], pl[kk][1]);
            split_pack(s[2 * kk + 1][0], s[2 * kk + 1][1], ph[kk][2], pl[kk][2]);
            split_pack(s[2 * kk + 1][2], s[2 * kk + 1][3], ph[kk][3], pl[kk][3]);
        }

#pragma unroll
        for (int dg = 0; dg < 4; dg++) {
            uint32_t vh[4][4], vl[4][4];
#pragma unroll
            for (int kk = 0; kk < 4; kk++) {
                uint32_t ad = sKhi + (uint32_t)(kk * 16 + t_r + (t_m & 1) * 8) * ATT_ROWB
                            + dg * 32 + (t_m >> 1) * 16;
                LDSM_X4_T(vh[kk][0], vh[kk][1], vh[kk][2], vh[kk][3], ad);
                LDSM_X4_T(vl[kk][0], vl[kk][1], vl[kk][2], vl[kk][3], ad + ATT_MAT);
            }
#pragma unroll
            for (int kk = 0; kk < 4; kk++)
#pragma unroll
                for (int sj = 0; sj < 2; sj++) {
                    float* cc = o[dg * 2 + sj];
                    MMA_BF16(cc[0], cc[1], cc[2], cc[3],
                             ph[kk][0], ph[kk][1], ph[kk][2], ph[kk][3],
                             vh[kk][sj * 2], vh[kk][sj * 2 + 1]);
                    MMA_BF16(cc[0], cc[1], cc[2], cc[3],
                             pl[kk][0], pl[kk][1], pl[kk][2], pl[kk][3],
                             vh[kk][sj * 2], vh[kk][sj * 2 + 1]);
                    MMA_BF16(cc[0], cc[1], cc[2], cc[3],
                             ph[kk][0], ph[kk][1], ph[kk][2], ph[kk][3],
                             vl[kk][sj * 2], vl[kk][sj * 2 + 1]);
                }
        }
        __syncthreads();
    }

    const float inv0 = 1.f / lrw[0];
    const float inv1 = 1.f / lrw[1];
    const int g = lane >> 2, t2 = (lane & 3) * 2;
    const size_t r0 = (size_t)(b * T + q0 + wid * 16 + g) * 1024 + h * 64 + t2;
    const size_t r1 = r0 + (size_t)8 * 1024;
#pragma unroll
    for (int nj = 0; nj < 8; nj++) {
        uint32_t hi, lo;
        split_pack(o[nj][0] * inv0, o[nj][1] * inv0, hi, lo);
        *(uint32_t*)(Ohi + r0 + nj * 8) = hi;
        *(uint32_t*)(Olo + r0 + nj * 8) = lo;
        split_pack(o[nj][2] * inv1, o[nj][3] * inv1, hi, lo);
        *(uint32_t*)(Ohi + r1 + nj * 8) = hi;
        *(uint32_t*)(Olo + r1 + nj * 8) = lo;
    }
}

// ---------------------------------------------------------------------------
extern "C" void kernel_launch(void* const* d_in, const int* in_sizes, int n_in,
                              void* d_out, int out_size)
{
    const float* x      = (const float*)d_in[0];
    const float* cosb   = (const float*)d_in[1];
    const float* sinb   = (const float*)d_in[2];
    const float* kv_w   = (const float*)d_in[3];
    const float* proj_w = (const float*)d_in[4];
    const int* wl       = (n_in >= 6) ? (const int*)d_in[5] : nullptr;

    const int T = in_sizes[1] / 32;
    const int C = 1024;
    const int B = in_sizes[0] / (T * C);
    const int M = B * T;
    const int total_heads = M * H_HEADS;

    __nv_bfloat16 *ahi, *alo, *bhi, *blo, *qhi, *qlo, *kvhi, *kvlo;
    cudaGetSymbolAddress((void**)&ahi,  g_ahi);
    cudaGetSymbolAddress((void**)&alo,  g_alo);
    cudaGetSymbolAddress((void**)&bhi,  g_bhi);
    cudaGetSymbolAddress((void**)&blo,  g_blo);
    cudaGetSymbolAddress((void**)&qhi,  g_qhi);
    cudaGetSymbolAddress((void**)&qlo,  g_qlo);
    cudaGetSymbolAddress((void**)&kvhi, g_kvhi);
    cudaGetSymbolAddress((void**)&kvlo, g_kvlo);

    cudaFuncSetAttribute(gemm_mma<true>,  cudaFuncAttributeMaxDynamicSharedMemorySize, GEMM_SMEM);
    cudaFuncSetAttribute(gemm_mma<false>, cudaFuncAttributeMaxDynamicSharedMemorySize, GEMM_SMEM);

    {
        int blocks = (total_heads + 7) / 8;
        prep_q<<<blocks, 256>>>(x, cosb, sinb, ahi, alo, qhi, qlo,
                                0.125f * LOG2E, T, total_heads);
    }
    split_bf16<<<(C * C / 4 + 255) / 256, 256>>>(kv_w, bhi, blo, C * C / 4);
    {
        dim3 grid(C / 128, M / 128);
        gemm_mma<true><<<grid, 256, GEMM_SMEM>>>(ahi, alo, bhi, blo, nullptr,
                                                 cosb, sinb, kvhi, kvlo, M, C, C, T);
    }
    {
        dim3 grid(T / 64, H_HEADS, B);
        attn_mma<<<grid, 128>>>(qhi, qlo, kvhi, kvlo, ahi, alo, wl, T);
    }
    split_bf16<<<(C * C / 4 + 255) / 256, 256>>>(proj_w, bhi, blo, C * C / 4);
    {
        dim3 grid(C / 128, M / 128);
        gemm_mma<false><<<grid, 256, GEMM_SMEM>>>(ahi, alo, bhi, blo, (float*)d_out,
                                                  nullptr, nullptr, nullptr, nullptr, M, C, C, T);
    }
}

// round 7
// speedup vs baseline: 1.0703x; 1.0703x over previous
#include <cuda_runtime.h>
#include <cuda_bf16.h>
#include <cstdint>

#define H_HEADS 16
#define DHEAD   64
#define RMS_EPS 1.1920928955078125e-07f
#define MAXTOK  4096
#define LOG2E   1.4426950408889634f
#define FIXMAX  12.0f   // scores in exp2 domain bounded by 8*log2e = 11.54

// ---------------- scratch ----------------
__device__ __nv_bfloat16 g_ahi [MAXTOK * 1024];
__device__ __nv_bfloat16 g_alo [MAXTOK * 1024];
__device__ __nv_bfloat16 g_bhi [1024 * 1024];
__device__ __nv_bfloat16 g_blo [1024 * 1024];
__device__ __nv_bfloat16 g_qhi [MAXTOK * 1024];
__device__ __nv_bfloat16 g_qlo [MAXTOK * 1024];
__device__ __nv_bfloat16 g_kvhi[MAXTOK * 1024];
__device__ __nv_bfloat16 g_kvlo[MAXTOK * 1024];

// ---------------- helpers ----------------
__device__ __forceinline__ uint32_t smem_u32(const void* p) {
    uint32_t a;
    asm("{ .reg .u64 t; cvta.to.shared.u64 t, %1; cvt.u32.u64 %0, t; }" : "=r"(a) : "l"(p));
    return a;
}

#define LDSM_X4(r0, r1, r2, r3, addr) \
    asm volatile("ldmatrix.sync.aligned.m8n8.x4.shared.b16 {%0,%1,%2,%3}, [%4];" \
                 : "=r"(r0), "=r"(r1), "=r"(r2), "=r"(r3) : "r"(addr))

#define LDSM_X4_T(r0, r1, r2, r3, addr) \
    asm volatile("ldmatrix.sync.aligned.m8n8.x4.trans.shared.b16 {%0,%1,%2,%3}, [%4];" \
                 : "=r"(r0), "=r"(r1), "=r"(r2), "=r"(r3) : "r"(addr))

#define MMA_BF16(c0, c1, c2, c3, a0, a1, a2, a3, b0, b1) \
    asm volatile("mma.sync.aligned.m16n8k16.row.col.f32.bf16.bf16.f32 " \
                 "{%0,%1,%2,%3}, {%4,%5,%6,%7}, {%8,%9}, {%0,%1,%2,%3};" \
                 : "+f"(c0), "+f"(c1), "+f"(c2), "+f"(c3) \
                 : "r"(a0), "r"(a1), "r"(a2), "r"(a3), "r"(b0), "r"(b1))

#define CP16(saddr, gptr) \
    asm volatile("cp.async.cg.shared.global [%0], [%1], 16;" :: "r"(saddr), "l"(gptr))
#define CP_COMMIT() asm volatile("cp.async.commit_group;" ::: "memory")
#define CP_WAIT1()  asm volatile("cp.async.wait_group 1;" ::: "memory")
#define CP_WAIT0()  asm volatile("cp.async.wait_group 0;" ::: "memory")

__device__ __forceinline__ uint32_t pack_bf2(__nv_bfloat16 a, __nv_bfloat16 b) {
    __nv_bfloat162 t(a, b);
    return *(uint32_t*)&t;
}
__device__ __forceinline__ void split_pack(float x, float y, uint32_t& hi, uint32_t& lo) {
    __nv_bfloat16 hx = __float2bfloat16(x), hy = __float2bfloat16(y);
    __nv_bfloat16 lx = __float2bfloat16(x - __bfloat162float(hx));
    __nv_bfloat16 ly = __float2bfloat16(y - __bfloat162float(hy));
    hi = pack_bf2(hx, hy);
    lo = pack_bf2(lx, ly);
}

// ---------------------------------------------------------------------------
// split fp32 -> bf16 hi + bf16 lo (weights)
// ---------------------------------------------------------------------------
__global__ __launch_bounds__(256) void split_bf16(
    const float* __restrict__ in, __nv_bfloat16* __restrict__ hi,
    __nv_bfloat16* __restrict__ lo, int n4)
{
    int i = blockIdx.x * blockDim.x + threadIdx.x;
    if (i >= n4) return;
    float4 v = ((const float4*)in)[i];
    uint32_t h0, l0, h1, l1;
    split_pack(v.x, v.y, h0, l0);
    split_pack(v.z, v.w, h1, l1);
    ((uint32_t*)hi)[2 * i]     = h0;
    ((uint32_t*)hi)[2 * i + 1] = h1;
    ((uint32_t*)lo)[2 * i]     = l0;
    ((uint32_t*)lo)[2 * i + 1] = l1;
}

// ---------------------------------------------------------------------------
// prep_q: x -> raw split [M,C] + roped/rms/scaled q split [B,H,T,D]
// ---------------------------------------------------------------------------
__global__ __launch_bounds__(256) void prep_q(
    const float* __restrict__ x, const float* __restrict__ cosb,
    const float* __restrict__ sinb,
    __nv_bfloat16* __restrict__ ahi, __nv_bfloat16* __restrict__ alo,
    __nv_bfloat16* __restrict__ qhi, __nv_bfloat16* __restrict__ qlo,
    float qscale, int T, int total_heads)
{
    int w = blockIdx.x * 8 + (threadIdx.x >> 5);
    if (w >= total_heads) return;
    int lane = threadIdx.x & 31;
    int h = w % H_HEADS;
    int t = (w / H_HEADS) % T;
    int b = w / (H_HEADS * T);

    size_t ibase = (size_t)w * DHEAD;
    float x1 = x[ibase + lane];
    float x2 = x[ibase + 32 + lane];

    {
        __nv_bfloat16 h1 = __float2bfloat16(x1);
        __nv_bfloat16 h2 = __float2bfloat16(x2);
        ahi[ibase + lane]      = h1;
        ahi[ibase + 32 + lane] = h2;
        alo[ibase + lane]      = __float2bfloat16(x1 - __bfloat162float(h1));
        alo[ibase + 32 + lane] = __float2bfloat16(x2 - __bfloat162float(h2));
    }

    float c  = cosb[t * 32 + lane];
    float s  = sinb[t * 32 + lane];
    float o1 = x1 * c + x2 * s;
    float o2 = -x1 * s + x2 * c;

    float ss = o1 * o1 + o2 * o2;
#pragma unroll
    for (int off = 16; off; off >>= 1)
        ss += __shfl_xor_sync(0xffffffffu, ss, off);
    float r = rsqrtf(ss * (1.0f / 64.0f) + RMS_EPS) * qscale;

    o1 *= r; o2 *= r;
    __nv_bfloat16 h1 = __float2bfloat16(o1);
    __nv_bfloat16 h2 = __float2bfloat16(o2);
    size_t obase = ((size_t)(b * H_HEADS + h) * T + t) * DHEAD;
    qhi[obase + lane]      = h1;
    qhi[obase + 32 + lane] = h2;
    qlo[obase + lane]      = __float2bfloat16(o1 - __bfloat162float(h1));
    qlo[obase + 32 + lane] = __float2bfloat16(o2 - __bfloat162float(h2));
}

// ---------------------------------------------------------------------------
// cp.async double-buffered split-precision NT GEMM (unchanged, it works)
// ---------------------------------------------------------------------------
#define KCH2   32
#define ROWB2  80
#define MATB2  (128 * ROWB2)
#define STB2   (4 * MATB2)
#define GEMM_SMEM (2 * STB2)

template <bool FUSE_ROPE>
__global__ __launch_bounds__(256) void gemm_mma(
    const __nv_bfloat16* __restrict__ Ahi, const __nv_bfloat16* __restrict__ Alo,
    const __nv_bfloat16* __restrict__ Bhi, const __nv_bfloat16* __restrict__ Blo,
    float* __restrict__ C,
    const float* __restrict__ cosb, const float* __restrict__ sinb,
    __nv_bfloat16* __restrict__ Ohi, __nv_bfloat16* __restrict__ Olo,
    int M, int N, int K, int T)
{
    extern __shared__ char smem[];
    const uint32_t sb = smem_u32(smem);

    const int tid  = threadIdx.x;
    const int wid  = tid >> 5;
    const int lane = tid & 31;
    const int m0 = blockIdx.y * 128, n0 = blockIdx.x * 128;

    const int wm = (wid & 3) * 32;
    const int wn = (wid >> 2) * 64;

    const int a_row = (lane & 7) + (lane & 8);
    const int a_col = (lane >> 4) * 16;
    const int b_row = (lane & 7) + ((lane >> 4) & 1) * 8;
    const int b_col = ((lane >> 3) & 1) * 16;

    const int grow = tid >> 1;
    const uint32_t s_off = (uint32_t)grow * ROWB2 + (tid & 1) * 32;
    const int gelem = (tid & 1) * 16;

    const __nv_bfloat16* gAh = Ahi + (size_t)(m0 + grow) * K + gelem;
    const __nv_bfloat16* gAl = Alo + (size_t)(m0 + grow) * K + gelem;
    const __nv_bfloat16* gBh = Bhi + (size_t)(n0 + grow) * K + gelem;
    const __nv_bfloat16* gBl = Blo + (size_t)(n0 + grow) * K + gelem;

    float c[2][8][4];
#pragma unroll
    for (int i = 0; i < 2; i++)
#pragma unroll
        for (int j = 0; j < 8; j++)
#pragma unroll
            for (int e = 0; e < 4; e++) c[i][j][e] = 0.f;

    const int nchunk = K / KCH2;

    auto fill = [&](int stage, int ch) {
        const int k0 = ch * KCH2;
        uint32_t s0 = sb + stage * STB2 + s_off;
        const __nv_bfloat16* a0 = gAh + k0;
        const __nv_bfloat16* a1 = gAl + k0;
        const __nv_bfloat16* b0 = gBh + k0;
        const __nv_bfloat16* b1 = gBl + k0;
        CP16(s0,                 a0);      CP16(s0 + 16,                 a0 + 8);
        CP16(s0 + MATB2,         a1);      CP16(s0 + MATB2 + 16,         a1 + 8);
        CP16(s0 + 2 * MATB2,     b0);      CP16(s0 + 2 * MATB2 + 16,     b0 + 8);
        CP16(s0 + 3 * MATB2,     b1);      CP16(s0 + 3 * MATB2 + 16,     b1 + 8);
    };

    fill(0, 0);
    CP_COMMIT();

    for (int ch = 0; ch < nchunk; ch++) {
        const int st = ch & 1;
        if (ch + 1 < nchunk) { fill(st ^ 1, ch + 1); CP_COMMIT(); CP_WAIT1(); }
        else                 { CP_WAIT0(); }
        __syncthreads();

        const uint32_t base = sb + st * STB2;
        const uint32_t sAhi = base, sBhi = base + 2 * MATB2;

#pragma unroll
        for (int ks = 0; ks < 2; ks++) {
            const int kb = ks * 32;
            uint32_t ah[2][4], al[2][4], bh[4][4], bl[4][4];
#pragma unroll
            for (int mi = 0; mi < 2; mi++) {
                uint32_t addr = sAhi + (uint32_t)(wm + mi * 16 + a_row) * ROWB2 + kb + a_col;
                LDSM_X4(ah[mi][0], ah[mi][1], ah[mi][2], ah[mi][3], addr);
                addr += MATB2;
                LDSM_X4(al[mi][0], al[mi][1], al[mi][2], al[mi][3], addr);
            }
#pragma unroll
            for (int nb = 0; nb < 4; nb++) {
                uint32_t addr = sBhi + (uint32_t)(wn + nb * 16 + b_row) * ROWB2 + kb + b_col;
                LDSM_X4(bh[nb][0], bh[nb][1], bh[nb][2], bh[nb][3], addr);
                addr += MATB2;
                LDSM_X4(bl[nb][0], bl[nb][1], bl[nb][2], bl[nb][3], addr);
            }
#pragma unroll
            for (int mi = 0; mi < 2; mi++)
#pragma unroll
                for (int nb = 0; nb < 4; nb++)
#pragma unroll
                    for (int sj = 0; sj < 2; sj++) {
                        float* cc = c[mi][nb * 2 + sj];
                        MMA_BF16(cc[0], cc[1], cc[2], cc[3],
                                 ah[mi][0], ah[mi][1], ah[mi][2], ah[mi][3],
                                 bh[nb][sj * 2], bh[nb][sj * 2 + 1]);
                        MMA_BF16(cc[0], cc[1], cc[2], cc[3],
                                 ah[mi][0], ah[mi][1], ah[mi][2], ah[mi][3],
                                 bl[nb][sj * 2], bl[nb][sj * 2 + 1]);
                        MMA_BF16(cc[0], cc[1], cc[2], cc[3],
                                 al[mi][0], al[mi][1], al[mi][2], al[mi][3],
                                 bh[nb][sj * 2], bh[nb][sj * 2 + 1]);
                    }
        }
        __syncthreads();
    }

    const int g  = lane >> 2;
    const int t2 = (lane & 3) * 2;

    if (!FUSE_ROPE) {
#pragma unroll
        for (int mi = 0; mi < 2; mi++) {
            float* r0 = C + (size_t)(m0 + wm + mi * 16 + g) * N + n0 + wn + t2;
            float* r1 = r0 + 8 * N;
#pragma unroll
            for (int nj = 0; nj < 8; nj++) {
                *(float2*)(r0 + nj * 8) = make_float2(c[mi][nj][0], c[mi][nj][1]);
                *(float2*)(r1 + nj * 8) = make_float2(c[mi][nj][2], c[mi][nj][3]);
            }
        }
    } else {
        const int h = (n0 + wn) >> 6;
#pragma unroll
        for (int mi = 0; mi < 2; mi++) {
#pragma unroll
            for (int half = 0; half < 2; half++) {
                const int m = m0 + wm + mi * 16 + g + half * 8;
                const int b = m / T, t = m % T;
                float o1[4][2], o2[4][2];
                float ss = 0.f;
#pragma unroll
                for (int nj = 0; nj < 4; nj++) {
#pragma unroll
                    for (int e = 0; e < 2; e++) {
                        const int d = nj * 8 + t2 + e;
                        float x1 = c[mi][nj][half * 2 + e];
                        float x2 = c[mi][nj + 4][half * 2 + e];
                        float co = cosb[t * 32 + d];
                        float si = sinb[t * 32 + d];
                        float a = x1 * co + x2 * si;
                        float bb = -x1 * si + x2 * co;
                        o1[nj][e] = a; o2[nj][e] = bb;
                        ss += a * a + bb * bb;
                    }
                }
                ss += __shfl_xor_sync(0xffffffffu, ss, 1);
                ss += __shfl_xor_sync(0xffffffffu, ss, 2);
                float r = rsqrtf(ss * (1.0f / 64.0f) + RMS_EPS);
                const size_t ob = ((size_t)(b * H_HEADS + h) * T + t) * DHEAD + t2;
#pragma unroll
                for (int nj = 0; nj < 4; nj++) {
                    uint32_t hi, lo;
                    split_pack(o1[nj][0] * r, o1[nj][1] * r, hi, lo);
                    *(uint32_t*)(Ohi + ob + nj * 8) = hi;
                    *(uint32_t*)(Olo + ob + nj * 8) = lo;
                    split_pack(o2[nj][0] * r, o2[nj][1] * r, hi, lo);
                    *(uint32_t*)(Ohi + ob + 32 + nj * 8) = hi;
                    *(uint32_t*)(Olo + ob + 32 + nj * 8) = lo;
                }
            }
        }
    }
}

// ---------------------------------------------------------------------------
// Tensor-core sliding-window flash attention (R5 load scheme, fixed-max softmax)
// ---------------------------------------------------------------------------
#define ATT_ROWB 144
#define ATT_MAT  (64 * ATT_ROWB)

__global__ __launch_bounds__(128) void attn_mma(
    const __nv_bfloat16* __restrict__ Qhi, const __nv_bfloat16* __restrict__ Qlo,
    const __nv_bfloat16* __restrict__ KVhi, const __nv_bfloat16* __restrict__ KVlo,
    __nv_bfloat16* __restrict__ Ohi, __nv_bfloat16* __restrict__ Olo,
    const int* __restrict__ wl, int T)
{
    __shared__ char smc[2 * ATT_MAT];
    const uint32_t sKhi = smem_u32(smc);

    const int tid = threadIdx.x, wid = tid >> 5, lane = tid & 31;
    const int qt = blockIdx.x, h = blockIdx.y, b = blockIdx.z;
    const int q0 = qt * 64;
    const int W = *wl;
    const size_t hb = (size_t)(b * H_HEADS + h) * T * DHEAD;

    const int lrow = tid >> 1;
    const uint32_t s_off = (uint32_t)lrow * ATT_ROWB + (tid & 1) * 64;
    const int gcol = (tid & 1) * 32;

    const int a_row  = (lane & 7) + (lane & 8);
    const int a_colB = (lane >> 4) * 16;
    const int b_row  = (lane & 7) + ((lane >> 4) & 1) * 8;
    const int b_colB = ((lane >> 3) & 1) * 16;
    const int t_m = lane >> 3, t_r = lane & 7;

    // stage Q through smem -> fragments
    {
        const uint4* sh = (const uint4*)(Qhi + hb + (size_t)(q0 + lrow) * DHEAD + gcol);
        const uint4* sl = (const uint4*)(Qlo + hb + (size_t)(q0 + lrow) * DHEAD + gcol);
#pragma unroll
        for (int j = 0; j < 4; j++) {
            *(uint4*)(smc + (s_off + j * 16)) = sh[j];
            *(uint4*)(smc + ATT_MAT + (s_off + j * 16)) = sl[j];
        }
    }
    __syncthreads();
    uint32_t qh[4][4], ql[4][4];
#pragma unroll
    for (int kc = 0; kc < 4; kc++) {
        uint32_t ad = sKhi + (uint32_t)(wid * 16 + a_row) * ATT_ROWB + kc * 32 + a_colB;
        LDSM_X4(qh[kc][0], qh[kc][1], qh[kc][2], qh[kc][3], ad);
        LDSM_X4(ql[kc][0], ql[kc][1], ql[kc][2], ql[kc][3], ad + ATT_MAT);
    }

    float o[8][4];
#pragma unroll
    for (int i = 0; i < 8; i++)
#pragma unroll
        for (int e = 0; e < 4; e++) o[i][e] = 0.f;
    float lrw[2] = {0.f, 0.f};

    int lo_t = q0 - W; if (lo_t < 0) lo_t = 0;
    const int kt_lo = lo_t >> 6;

    for (int kt = kt_lo; kt <= qt; kt++) {
        const int k0 = kt * 64;
        __syncthreads();
        {
            const uint4* sh = (const uint4*)(KVhi + hb + (size_t)(k0 + lrow) * DHEAD + gcol);
            const uint4* sl = (const uint4*)(KVlo + hb + (size_t)(k0 + lrow) * DHEAD + gcol);
#pragma unroll
            for (int j = 0; j < 4; j++) {
                *(uint4*)(smc + (s_off + j * 16)) = sh[j];
                *(uint4*)(smc + ATT_MAT + (s_off + j * 16)) = sl[j];
            }
        }
        __syncthreads();

        float s[8][4];
#pragma unroll
        for (int i = 0; i < 8; i++)
#pragma unroll
            for (int e = 0; e < 4; e++) s[i][e] = 0.f;

#pragma unroll
        for (int n16 = 0; n16 < 4; n16++) {
            uint32_t bh[4][4], bl[4][4];
#pragma unroll
            for (int kc = 0; kc < 4; kc++) {
                uint32_t ad = sKhi + (uint32_t)(n16 * 16 + b_row) * ATT_ROWB + kc * 32 + b_colB;
                LDSM_X4(bh[kc][0], bh[kc][1], bh[kc][2], bh[kc][3], ad);
                LDSM_X4(bl[kc][0], bl[kc][1], bl[kc][2], bl[kc][3], ad + ATT_MAT);
            }
#pragma unroll
            for (int kc = 0; kc < 4; kc++)
#pragma unroll
                for (int sj = 0; sj < 2; sj++) {
                    float* cc = s[n16 * 2 + sj];
                    MMA_BF16(cc[0], cc[1], cc[2], cc[3],
                             qh[kc][0], qh[kc][1], qh[kc][2], qh[kc][3],
                             bh[kc][sj * 2], bh[kc][sj * 2 + 1]);
                    MMA_BF16(cc[0], cc[1], cc[2], cc[3],
                             qh[kc][0], qh[kc][1], qh[kc][2], qh[kc][3],
                             bl[kc][sj * 2], bl[kc][sj * 2 + 1]);
                    MMA_BF16(cc[0], cc[1], cc[2], cc[3],
                             ql[kc][0], ql[kc][1], ql[kc][2], ql[kc][3],
                             bh[kc][sj * 2], bh[kc][sj * 2 + 1]);
                }
        }

        const bool fullt = (kt < qt) && (q0 + 63 - k0 <= W);
        if (!fullt) {
            const int qr = q0 + wid * 16 + (lane >> 2);
#pragma unroll
            for (int nb = 0; nb < 8; nb++) {
                const int kb = k0 + nb * 8 + (lane & 3) * 2;
#pragma unroll
                for (int e = 0; e < 4; e++) {
                    int qq = qr + ((e >= 2) ? 8 : 0);
                    int kk = kb + (e & 1);
                    if (kk > qq || qq - kk > W) s[nb][e] = -1e30f;
                }
            }
        }

        // ---- fixed-max softmax: p = exp2(s - FIXMAX), no rescale needed ----
        uint32_t ph[4][4], pl[4][4];
#pragma unroll
        for (int r = 0; r < 2; r++) {
            float rs = 0.f;
#pragma unroll
            for (int nb = 0; nb < 8; nb++) {
#pragma unroll
                for (int e = 0; e < 2; e++) {
                    float p = exp2f(s[nb][r * 2 + e] - FIXMAX);
                    s[nb][r * 2 + e] = p;
                    rs += p;
                }
            }
            rs += __shfl_xor_sync(0xffffffffu, rs, 1);
            rs += __shfl_xor_sync(0xffffffffu, rs, 2);
            lrw[r] += rs;
        }

#pragma unroll
        for (int kk = 0; kk < 4; kk++) {
            split_pack(s[2 * kk][0],     s[2 * kk][1],     ph[kk][0], pl[kk][0]);
            split_pack(s[2 * kk][2],     s[2 * kk][3],     ph[kk][1], pl[kk][1]);
            split_pack(s[2 * kk + 1][0], s[2 * kk + 1][1], ph[kk][2], pl[kk][2]);
            split_pack(s[2 * kk + 1][2], s[2 * kk + 1][3], ph[kk][3], pl[kk][3]);
        }

#pragma unroll
        for (int dg = 0; dg < 4; dg++) {
            uint32_t vh[4][4], vl[4][4];
#pragma unroll
            for (int kk = 0; kk < 4; kk++) {
                uint32_t ad = sKhi + (uint32_t)(kk * 16 + t_r + (t_m & 1) * 8) * ATT_ROWB
                            + dg * 32 + (t_m >> 1) * 16;
                LDSM_X4_T(vh[kk][0], vh[kk][1], vh[kk][2], vh[kk][3], ad);
                LDSM_X4_T(vl[kk][0], vl[kk][1], vl[kk][2], vl[kk][3], ad + ATT_MAT);
            }
#pragma unroll
            for (int kk = 0; kk < 4; kk++)
#pragma unroll
                for (int sj = 0; sj < 2; sj++) {
                    float* cc = o[dg * 2 + sj];
                    MMA_BF16(cc[0], cc[1], cc[2], cc[3],
                             ph[kk][0], ph[kk][1], ph[kk][2], ph[kk][3],
                             vh[kk][sj * 2], vh[kk][sj * 2 + 1]);
                    MMA_BF16(cc[0], cc[1], cc[2], cc[3],
                             pl[kk][0], pl[kk][1], pl[kk][2], pl[kk][3],
                             vh[kk][sj * 2], vh[kk][sj * 2 + 1]);
                    MMA_BF16(cc[0], cc[1], cc[2], cc[3],
                             ph[kk][0], ph[kk][1], ph[kk][2], ph[kk][3],
                             vl[kk][sj * 2], vl[kk][sj * 2 + 1]);
                }
        }
    }

    const float inv0 = 1.f / lrw[0];
    const float inv1 = 1.f / lrw[1];
    const int g = lane >> 2, t2 = (lane & 3) * 2;
    const size_t r0 = (size_t)(b * T + q0 + wid * 16 + g) * 1024 + h * 64 + t2;
    const size_t r1 = r0 + (size_t)8 * 1024;
#pragma unroll
    for (int nj = 0; nj < 8; nj++) {
        uint32_t hi, lo;
        split_pack(o[nj][0] * inv0, o[nj][1] * inv0, hi, lo);
        *(uint32_t*)(Ohi + r0 + nj * 8) = hi;
        *(uint32_t*)(Olo + r0 + nj * 8) = lo;
        split_pack(o[nj][2] * inv1, o[nj][3] * inv1, hi, lo);
        *(uint32_t*)(Ohi + r1 + nj * 8) = hi;
        *(uint32_t*)(Olo + r1 + nj * 8) = lo;
    }
}

// ---------------------------------------------------------------------------
extern "C" void kernel_launch(void* const* d_in, const int* in_sizes, int n_in,
                              void* d_out, int out_size)
{
    const float* x      = (const float*)d_in[0];
    const float* cosb   = (const float*)d_in[1];
    const float* sinb   = (const float*)d_in[2];
    const float* kv_w   = (const float*)d_in[3];
    const float* proj_w = (const float*)d_in[4];
    const int* wl       = (n_in >= 6) ? (const int*)d_in[5] : nullptr;

    const int T = in_sizes[1] / 32;
    const int C = 1024;
    const int B = in_sizes[0] / (T * C);
    const int M = B * T;
    const int total_heads = M * H_HEADS;

    __nv_bfloat16 *ahi, *alo, *bhi, *blo, *qhi, *qlo, *kvhi, *kvlo;
    cudaGetSymbolAddress((void**)&ahi,  g_ahi);
    cudaGetSymbolAddress((void**)&alo,  g_alo);
    cudaGetSymbolAddress((void**)&bhi,  g_bhi);
    cudaGetSymbolAddress((void**)&blo,  g_blo);
    cudaGetSymbolAddress((void**)&qhi,  g_qhi);
    cudaGetSymbolAddress((void**)&qlo,  g_qlo);
    cudaGetSymbolAddress((void**)&kvhi, g_kvhi);
    cudaGetSymbolAddress((void**)&kvlo, g_kvlo);

    cudaFuncSetAttribute(gemm_mma<true>,  cudaFuncAttributeMaxDynamicSharedMemorySize, GEMM_SMEM);
    cudaFuncSetAttribute(gemm_mma<false>, cudaFuncAttributeMaxDynamicSharedMemorySize, GEMM_SMEM);

    {
        int blocks = (total_heads + 7) / 8;
        prep_q<<<blocks, 256>>>(x, cosb, sinb, ahi, alo, qhi, qlo,
                                0.125f * LOG2E, T, total_heads);
    }
    split_bf16<<<(C * C / 4 + 255) / 256, 256>>>(kv_w, bhi, blo, C * C / 4);
    {
        dim3 grid(C / 128, M / 128);
        gemm_mma<true><<<grid, 256, GEMM_SMEM>>>(ahi, alo, bhi, blo, nullptr,
                                                 cosb, sinb, kvhi, kvlo, M, C, C, T);
    }
    {
        dim3 grid(T / 64, H_HEADS, B);
        attn_mma<<<grid, 128>>>(qhi, qlo, kvhi, kvlo, ahi, alo, wl, T);
    }
    split_bf16<<<(C * C / 4 + 255) / 256, 256>>>(proj_w, bhi, blo, C * C / 4);
    {
        dim3 grid(C / 128, M / 128);
        gemm_mma<false><<<grid, 256, GEMM_SMEM>>>(ahi, alo, bhi, blo, (float*)d_out,
                                                  nullptr, nullptr, nullptr, nullptr, M, C, C, T);
    }
}